// round 6
// baseline (speedup 1.0000x reference)
#include <cuda_runtime.h>
#include <cuda_bf16.h>

#define IMG_W 416
#define IMG_H 416
#define NCH   3
#define TPB   256
#define STRIPS 32
#define SROWS  13                    // 416 / 32
#define QROW   104                   // float4 quads per row
#define CS     (IMG_W * IMG_H)       // 173056
#define CS4    (CS / 4)
#define PB     4                     // patch blocks per sample

struct Affine {
    float t00, t01, t02, t10, t11, t12;
    int bx, by, bxe, bye;   // clamped pixel bbox (inclusive); bxe<bx if empty
};

__device__ __forceinline__ Affine compute_affine(const float* __restrict__ bb,
                                                 const float* __restrict__ angle,
                                                 const int*   __restrict__ pos_ptr,
                                                 int n) {
    Affine A;
    float patch_ori = 300.0f;
    if (pos_ptr) {
        int pi = pos_ptr[0];
        patch_ori = (pi > 0 && pi < 1000000) ? (float)pi : __int_as_float(pi);
    }
    float x1 = bb[n * 6 + 0];
    float y1 = bb[n * 6 + 1];
    float x2 = bb[n * 6 + 2];
    float y2 = bb[n * 6 + 3];

    float bwv = (x2 - x1) * (float)IMG_W;
    float bhv = (y2 - y1) * (float)IMG_H;
    float cx  = (x1 + x2) * 0.5f;
    float cy  = (y1 + y2) * 0.5f - (y2 - y1) * 0.1f;
    float tx  = (0.5f - cx) * 2.0f;
    float ty  = (0.5f - cy) * 2.0f;
    float target = 0.2f * sqrtf(bwv * bwv + bhv * bhv);
    float scale  = __fdiv_rn(target, patch_ori);

    float a = angle[n];
    float s = sinf(a);
    float c = cosf(a);

    A.t00 = __fdiv_rn(c, scale);
    A.t01 = __fdiv_rn(s, scale);
    A.t02 = __fdiv_rn(tx * c + ty * s, scale);
    A.t10 = __fdiv_rn(-s, scale);
    A.t11 = __fdiv_rn(c, scale);
    A.t12 = __fdiv_rn(-tx * s + ty * c, scale);

    // Pixel-space map constants: ix = t00*x + t01*y + cx2
    float cx2 = 207.5f - 207.5f * A.t00 - 207.5f * A.t01 + 208.0f * A.t02;
    float cy2 = 207.5f - 207.5f * A.t10 - 207.5f * A.t11 + 208.0f * A.t12;

    // Output-space bbox = preimage of source square [-1,416]^2
    float det  = A.t00 * A.t11 - A.t01 * A.t10;
    float rdet = __fdiv_rn(1.0f, det);
    float xmin = 1e9f, xmax = -1e9f, ymin = 1e9f, ymax = -1e9f;
#pragma unroll
    for (int k = 0; k < 4; k++) {
        float u  = (k & 1) ? 416.0f : -1.0f;
        float v  = (k & 2) ? 416.0f : -1.0f;
        float du = u - cx2;
        float dv = v - cy2;
        float px = (A.t11 * du - A.t01 * dv) * rdet;
        float py = (A.t00 * dv - A.t10 * du) * rdet;
        xmin = fminf(xmin, px); xmax = fmaxf(xmax, px);
        ymin = fminf(ymin, py); ymax = fmaxf(ymax, py);
    }
    A.bx  = max(0, (int)floorf(xmin) - 2);
    A.by  = max(0, (int)floorf(ymin) - 2);
    A.bxe = min(IMG_W - 1, (int)ceilf(xmax) + 2);
    A.bye = min(IMG_H - 1, (int)ceilf(ymax) + 2);
    return A;
}

__global__ void __launch_bounds__(TPB)
fused_kernel(const float* __restrict__ img,
             const float* __restrict__ bb,
             const float* __restrict__ angle,
             const int*   __restrict__ pos_ptr,
             float* __restrict__ out) {
    const int n = blockIdx.y;
    const Affine A = compute_affine(bb, angle, pos_ptr, n);

    const bool haveBox = (A.bxe >= A.bx) && (A.bye >= A.by);
    const int qx0 = A.bx >> 2;
    const int qx1 = A.bxe >> 2;

    if (blockIdx.x < STRIPS) {
        // ---------------- Fill role: pure zero stores, skip bbox quads ----------
        const int y0s = blockIdx.x * SROWS;
        float4* obase4 = (float4*)(out + (size_t)n * NCH * CS);
        const float4 z = make_float4(0.f, 0.f, 0.f, 0.f);
#pragma unroll
        for (int c = 0; c < NCH; c++) {
            float4* cb = obase4 + c * CS4;
            for (int i = threadIdx.x; i < SROWS * QROW; i += TPB) {
                int r = i / QROW;
                int q = i - r * QROW;
                int y = y0s + r;
                bool skip = haveBox && (y >= A.by) && (y <= A.bye)
                                    && (q >= qx0) && (q <= qx1);
                if (!skip) cb[y * QROW + q] = z;
            }
        }
        return;
    }

    // ---------------- Patch role: exclusively own the bbox quad-rectangle ------
    if (!haveBox) return;
    const int pb = blockIdx.x - STRIPS;          // 0..PB-1
    const int nq = qx1 - qx0 + 1;
    const int nr = A.bye - A.by + 1;
    const int total = nq * nr;

    const float t00 = A.t00, t01 = A.t01, t02 = A.t02;
    const float t10 = A.t10, t11 = A.t11, t12 = A.t12;

    const float* base = img + (size_t)n * NCH * CS;
    float* obase = out + (size_t)n * NCH * CS;

    for (int t = pb * TPB + threadIdx.x; t < total; t += PB * TPB) {
        const int r  = t / nq;
        const int q  = qx0 + (t - r * nq);
        const int yy = A.by + r;
        const int xbase = q * 4;

        const float ysv = __fdiv_rn(2.0f * (float)yy + 1.0f, (float)IMG_W) - 1.0f;
        const float Cx = fmaf(208.0f, fmaf(t01, ysv, t02), fmaf(-207.5f, t00, 207.5f));
        const float Cy = fmaf(208.0f, fmaf(t11, ysv, t12), fmaf(-207.5f, t10, 207.5f));

        float acc0[4], acc1[4], acc2[4];
#pragma unroll
        for (int p = 0; p < 4; p++) {
            const float xf = (float)(xbase + p);
            const float ix = fmaf(t00, xf, Cx);
            const float iy = fmaf(t10, xf, Cy);

            float fx0 = floorf(ix), fy0 = floorf(iy);
            int   x0  = (int)fx0,   y0  = (int)fy0;
            float wx1 = ix - fx0,   wy1 = iy - fy0;
            float wx0 = 1.0f - wx1, wy0 = 1.0f - wy1;

            bool vx0 = (x0 >= 0)  && (x0 < IMG_W);
            bool vx1 = (x0 >= -1) && (x0 < IMG_W - 1);
            bool vy0 = (y0 >= 0)  && (y0 < IMG_H);
            bool vy1 = (y0 >= -1) && (y0 < IMG_H - 1);

            float w00 = (vx0 && vy0) ? wx0 * wy0 : 0.0f;
            float w10 = (vx1 && vy0) ? wx1 * wy0 : 0.0f;
            float w01 = (vx0 && vy1) ? wx0 * wy1 : 0.0f;
            float w11 = (vx1 && vy1) ? wx1 * wy1 : 0.0f;

            float a0 = 0.f, a1 = 0.f, a2 = 0.f;
            int i00 = y0 * IMG_W + x0;
            if (w00 != 0.0f) {
                a0 = fmaf(w00, __ldg(base + i00), a0);
                a1 = fmaf(w00, __ldg(base + CS + i00), a1);
                a2 = fmaf(w00, __ldg(base + 2 * CS + i00), a2);
            }
            if (w10 != 0.0f) {
                int i = i00 + 1;
                a0 = fmaf(w10, __ldg(base + i), a0);
                a1 = fmaf(w10, __ldg(base + CS + i), a1);
                a2 = fmaf(w10, __ldg(base + 2 * CS + i), a2);
            }
            if (w01 != 0.0f) {
                int i = i00 + IMG_W;
                a0 = fmaf(w01, __ldg(base + i), a0);
                a1 = fmaf(w01, __ldg(base + CS + i), a1);
                a2 = fmaf(w01, __ldg(base + 2 * CS + i), a2);
            }
            if (w11 != 0.0f) {
                int i = i00 + IMG_W + 1;
                a0 = fmaf(w11, __ldg(base + i), a0);
                a1 = fmaf(w11, __ldg(base + CS + i), a1);
                a2 = fmaf(w11, __ldg(base + 2 * CS + i), a2);
            }
            acc0[p] = a0;
            acc1[p] = a1;
            acc2[p] = a2;
        }

        const int o = yy * IMG_W + xbase;
        *(float4*)(obase + o)          = make_float4(acc0[0], acc0[1], acc0[2], acc0[3]);
        *(float4*)(obase + o + CS)     = make_float4(acc1[0], acc1[1], acc1[2], acc1[3]);
        *(float4*)(obase + o + 2 * CS) = make_float4(acc2[0], acc2[1], acc2[2], acc2[3]);
    }
}

extern "C" void kernel_launch(void* const* d_in, const int* in_sizes, int n_in,
                              void* d_out, int out_size) {
    const float* img = (const float*)d_in[0];   // adv_patch_batch (B,L,C,H,W) f32
    const float* bb  = (const float*)d_in[1];   // bboxes_batch (B,L,6) f32
    const float* ang = (const float*)d_in[2];   // angle (B*L,) f32
    const int*   pos = (n_in > 3) ? (const int*)d_in[3] : nullptr;

    int N = in_sizes[2];                        // B*L = 128

    dim3 grid(STRIPS + PB, N);
    fused_kernel<<<grid, TPB>>>(img, bb, ang, pos, (float*)d_out);
}